// round 15
// baseline (speedup 1.0000x reference)
#include <cuda_runtime.h>
#include <cuda_bf16.h>
#include <mma.h>
#include <math.h>

using namespace nvcuda;

#define NBK  5
#define HD   32
#define DIN  4
#define TT   25
#define HIDD 64
#define TPB  256          // 8 warps; warp w owns gate n-tile [16w, 16w+16)
#define SPC  128          // samples per CTA (MMA M)
#define TILES 256
#define GRID (TILES*NBK)  // 1280

// ---- SMEM regions (bytes). A tiles are column-major [k][m] lda=136 (x2B). ----
#define SM_A0H 0          // h0 hi  [32][136] bf16 = 8704
#define SM_A0L 8704       // h0 lo
#define SM_A1H 17408      // h1 hi
#define SM_A1L 26112      // h1 lo
#define SM_AX  34816      // x packs [16][136] bf16 = 4352 (rows: xh,xh,xl,0 x4)
#define SM_W0H 39168      // W tiles row-major [128 gates(4j+g)][40] bf16 = 10240
#define SM_W0L 49408
#define SM_P1H 59648
#define SM_P1L 69888
#define SM_W1H 80128
#define SM_W1L 90368
#define SM_WX  100608     // [128][24] bf16 = 6144 (cols: Wxh,Wxl,Wxh,0)
#define SM_D   106752     // gates f32 [128][132] = 67584
#define SM_B0  174336     // bias0[128] f32, row 4j+g
#define SM_B1  174848
#define SM_SZ  175360     // -> 1 CTA/SM, 8 warps

#define LDA 136           // A leading dim (bf16 elems, mult of 8)
#define LDW 40            // W leading dim
#define LDX 24            // WX leading dim
#define LDD 132           // D leading dim (f32, mult of 4)

// MLP overlay (floats) into the W region after recurrence
#define OVF   (SM_W0H/4)
#define OV_W1 (OVF+0)
#define OV_B1 (OVF+2048)
#define OV_W2 (OVF+2112)
#define OV_B2 (OVF+6208)

static __device__ __forceinline__ float tanhfast(float x) {
    float y; asm("tanh.approx.f32 %0, %1;" : "=f"(y) : "f"(x)); return y;
}
static __device__ __forceinline__ float sigf(float v) {
    return fmaf(0.5f, tanhfast(0.5f * v), 0.5f);
}

typedef wmma::fragment<wmma::matrix_a, 16, 16, 16, __nv_bfloat16, wmma::col_major> FragA;
typedef wmma::fragment<wmma::matrix_b, 16, 16, 16, __nv_bfloat16, wmma::col_major> FragB;
typedef wmma::fragment<wmma::accumulator, 16, 16, 16, float> FragC;

__global__ void __launch_bounds__(TPB, 1) lstm_wmma(
    const float* __restrict__ x,    const float* __restrict__ mask,
    const float* __restrict__ Wih0, const float* __restrict__ Whh0,
    const float* __restrict__ bih0, const float* __restrict__ bhh0,
    const float* __restrict__ Wih1, const float* __restrict__ Whh1,
    const float* __restrict__ bih1, const float* __restrict__ bhh1,
    const float* __restrict__ W1,   const float* __restrict__ b1,
    const float* __restrict__ W2,   const float* __restrict__ b2,
    float* __restrict__ out)
{
    extern __shared__ char sm[];
    __nv_bfloat16* A0H = (__nv_bfloat16*)(sm + SM_A0H);
    __nv_bfloat16* A0L = (__nv_bfloat16*)(sm + SM_A0L);
    __nv_bfloat16* A1H = (__nv_bfloat16*)(sm + SM_A1H);
    __nv_bfloat16* A1L = (__nv_bfloat16*)(sm + SM_A1L);
    __nv_bfloat16* AX  = (__nv_bfloat16*)(sm + SM_AX);
    __nv_bfloat16* WX  = (__nv_bfloat16*)(sm + SM_WX);
    float* D   = (float*)(sm + SM_D);
    float* b0p = (float*)(sm + SM_B0);
    float* b1p = (float*)(sm + SM_B1);

    const int tid  = threadIdx.x;
    const int wid  = tid >> 5;
    const int ng   = wid * 16;                   // this warp's gate-column base
    const int ib   = 4 - (blockIdx.x >> 8);      // heavy blocks first
    const int tile = blockIdx.x & (TILES - 1);

    // ---- zero A region (h starts at 0; pads stay 0) and WX ----
    for (int i = tid; i < (SM_W0H - SM_A0H) / 16; i += TPB)
        ((uint4*)(sm + SM_A0H))[i] = make_uint4(0, 0, 0, 0);
    for (int i = tid; i < (SM_D - SM_WX) / 16; i += TPB)
        ((uint4*)(sm + SM_WX))[i] = make_uint4(0, 0, 0, 0);

    // ---- stage weights: hi/lo bf16 split, gate rows interleaved r = 4j+g ----
    {
        const float* srcs[3] = { Whh0 + ib * 4096, Wih1 + ib * 4096, Whh1 + ib * 4096 };
        __nv_bfloat16* WH[3] = { (__nv_bfloat16*)(sm + SM_W0H),
                                 (__nv_bfloat16*)(sm + SM_P1H),
                                 (__nv_bfloat16*)(sm + SM_W1H) };
        __nv_bfloat16* WL[3] = { (__nv_bfloat16*)(sm + SM_W0L),
                                 (__nv_bfloat16*)(sm + SM_P1L),
                                 (__nv_bfloat16*)(sm + SM_W1L) };
        for (int idx = tid; idx < 3 * 128 * 32; idx += TPB) {
            int m = idx >> 12, t = idx & 4095, sr = t >> 5, k = t & 31;
            int r = 4 * (sr & 31) + (sr >> 5);
            float w = srcs[m][sr * 32 + k];
            __nv_bfloat16 hb = __float2bfloat16(w);
            float lo = w - __bfloat162float(hb);
            WH[m][r * LDW + k] = hb;
            WL[m][r * LDW + k] = __float2bfloat16(lo);
        }
    }
    __syncthreads();   // WX zeros visible before scatter below
    for (int idx = tid; idx < 128 * DIN; idx += TPB) {
        int sr = idx >> 2, k = idx & 3;
        int r = 4 * (sr & 31) + (sr >> 5);
        float w = Wih0[ib * 512 + sr * DIN + k];
        __nv_bfloat16 hb = __float2bfloat16(w);
        float lo = w - __bfloat162float(hb);
        WX[r * LDX + k]     = hb;   // pairs with xh
        WX[r * LDX + 4 + k] = __float2bfloat16(lo);   // pairs with xh
        WX[r * LDX + 8 + k] = hb;   // pairs with xl
    }
    if (tid < 128) {
        int r = 4 * (tid & 31) + (tid >> 5);
        b0p[r] = bih0[ib * 128 + tid] + bhh0[ib * 128 + tid];
        b1p[r] = bih1[ib * 128 + tid] + bhh1[ib * 128 + tid];
    }
    __syncthreads();

    // ---- per-thread epilogue state: 2 threads/sample, 16 j each ----
    const int s  = tid & 127;        // sample
    const int jh = tid >> 7;         // j half: [16*jh, 16*jh+16)
    float c0r[16], c1r[16];
#pragma unroll
    for (int q = 0; q < 16; q++) { c0r[q] = 0.f; c1r[q] = 0.f; }

    const int Ti = 5 * (ib + 1);
    const float4* xb = (const float4*)x    + (size_t)(tile * SPC + s) * TT + (TT - Ti);
    const float4* mb = (const float4*)mask + (size_t)(tile * SPC + s) * TT + (TT - Ti);

    for (int st = 0; st < Ti; st++) {
        // ---- stage x packs (threads 0-127; rows 12-15 stay zero) ----
        if (tid < 128) {
            float4 xv = __ldg(xb + st), mv = __ldg(mb + st);
            float xm[4] = { xv.x * mv.x, xv.y * mv.y, xv.z * mv.z, xv.w * mv.w };
#pragma unroll
            for (int k = 0; k < 4; k++) {
                __nv_bfloat16 hb = __float2bfloat16(xm[k]);
                float lo = xm[k] - __bfloat162float(hb);
                AX[(k)     * LDA + s] = hb;
                AX[(k + 4) * LDA + s] = hb;
                AX[(k + 8) * LDA + s] = __float2bfloat16(lo);
            }
        }
        __syncthreads();

        // ================= layer 0 MMA: D = h0*Wh0(split) + x*Wx(split) ========
        for (int m = 0; m < 8; m++) {
            FragC c;
            wmma::fill_fragment(c, 0.0f);
#pragma unroll
            for (int kt = 0; kt < 2; kt++) {
                FragA ahh, ahl; FragB bh, bl;
                wmma::load_matrix_sync(ahh, A0H + kt * 16 * LDA + m * 16, LDA);
                wmma::load_matrix_sync(ahl, A0L + kt * 16 * LDA + m * 16, LDA);
                wmma::load_matrix_sync(bh, (__nv_bfloat16*)(sm + SM_W0H) + ng * LDW + kt * 16, LDW);
                wmma::load_matrix_sync(bl, (__nv_bfloat16*)(sm + SM_W0L) + ng * LDW + kt * 16, LDW);
                wmma::mma_sync(c, ahh, bh, c);
                wmma::mma_sync(c, ahh, bl, c);
                wmma::mma_sync(c, ahl, bh, c);
            }
            FragA ax; FragB bx;
            wmma::load_matrix_sync(ax, AX + m * 16, LDA);
            wmma::load_matrix_sync(bx, WX + ng * LDX, LDX);
            wmma::mma_sync(c, ax, bx, c);
            wmma::store_matrix_sync(D + m * 16 * LDD + ng, c, LDD, wmma::mem_row_major);
        }
        __syncthreads();

        // ---- layer 0 epilogue ----
#pragma unroll
        for (int q = 0; q < 16; q++) {
            const int j = jh * 16 + q;
            float4 gg = *(const float4*)(D + s * LDD + 4 * j);
            float4 bb = *(const float4*)(b0p + 4 * j);
            float ai = gg.x + bb.x, af = gg.y + bb.y;
            float ag = gg.z + bb.z, ao = gg.w + bb.w;
            float cc = sigf(af) * c0r[q] + sigf(ai) * tanhfast(ag);
            c0r[q] = cc;
            float h = sigf(ao) * tanhfast(cc);
            __nv_bfloat16 hb = __float2bfloat16(h);
            A0H[j * LDA + s] = hb;
            A0L[j * LDA + s] = __float2bfloat16(h - __bfloat162float(hb));
        }
        __syncthreads();

        // ========== layer 1 MMA: D = h0new*Wp1(split) + h1*Wh1(split) ==========
        for (int m = 0; m < 8; m++) {
            FragC c;
            wmma::fill_fragment(c, 0.0f);
#pragma unroll
            for (int kt = 0; kt < 2; kt++) {
                FragA ahh, ahl; FragB bh, bl;
                wmma::load_matrix_sync(ahh, A0H + kt * 16 * LDA + m * 16, LDA);
                wmma::load_matrix_sync(ahl, A0L + kt * 16 * LDA + m * 16, LDA);
                wmma::load_matrix_sync(bh, (__nv_bfloat16*)(sm + SM_P1H) + ng * LDW + kt * 16, LDW);
                wmma::load_matrix_sync(bl, (__nv_bfloat16*)(sm + SM_P1L) + ng * LDW + kt * 16, LDW);
                wmma::mma_sync(c, ahh, bh, c);
                wmma::mma_sync(c, ahh, bl, c);
                wmma::mma_sync(c, ahl, bh, c);
            }
#pragma unroll
            for (int kt = 0; kt < 2; kt++) {
                FragA ahh, ahl; FragB bh, bl;
                wmma::load_matrix_sync(ahh, A1H + kt * 16 * LDA + m * 16, LDA);
                wmma::load_matrix_sync(ahl, A1L + kt * 16 * LDA + m * 16, LDA);
                wmma::load_matrix_sync(bh, (__nv_bfloat16*)(sm + SM_W1H) + ng * LDW + kt * 16, LDW);
                wmma::load_matrix_sync(bl, (__nv_bfloat16*)(sm + SM_W1L) + ng * LDW + kt * 16, LDW);
                wmma::mma_sync(c, ahh, bh, c);
                wmma::mma_sync(c, ahh, bl, c);
                wmma::mma_sync(c, ahl, bh, c);
            }
            wmma::store_matrix_sync(D + m * 16 * LDD + ng, c, LDD, wmma::mem_row_major);
        }
        __syncthreads();

        // ---- layer 1 epilogue ----
#pragma unroll
        for (int q = 0; q < 16; q++) {
            const int j = jh * 16 + q;
            float4 gg = *(const float4*)(D + s * LDD + 4 * j);
            float4 bb = *(const float4*)(b1p + 4 * j);
            float ai = gg.x + bb.x, af = gg.y + bb.y;
            float ag = gg.z + bb.z, ao = gg.w + bb.w;
            float cc = sigf(af) * c1r[q] + sigf(ai) * tanhfast(ag);
            c1r[q] = cc;
            float h = sigf(ao) * tanhfast(cc);
            __nv_bfloat16 hb = __float2bfloat16(h);
            A1H[j * LDA + s] = hb;
            A1L[j * LDA + s] = __float2bfloat16(h - __bfloat162float(hb));
        }
        // A1 writes ordered before next step's L1 reads by next step's barriers;
        // D reads here ordered before next step's L0 D writes by the top barrier.
    }
    __syncthreads();   // final h1 visible; W region about to be overlaid

    // ---- read final h1 (hh + hl; err ~2^-18, negligible) ----
    float hr[HD];
#pragma unroll
    for (int k = 0; k < HD; k++)
        hr[k] = __bfloat162float(A1H[k * LDA + s]) + __bfloat162float(A1L[k * LDA + s]);

    // ---- MLP head: 2 threads per sample, exact gelu ----
    float* ov = (float*)sm;
    for (int idx = tid; idx < HIDD * HD; idx += TPB)   ov[OV_W1 + idx] = W1[idx];
    for (int idx = tid; idx < HIDD * HIDD; idx += TPB) {
        int n = idx / HIDD, m = idx % HIDD;
        ov[OV_W2 + m * HIDD + n] = W2[idx];            // transposed [m][n]
    }
    if (tid < HIDD) { ov[OV_B1 + tid] = b1[tid]; ov[OV_B2 + tid] = b2[tid]; }
    __syncthreads();

    const int half = jh;             // which 32 outputs
    float acc2[HIDD / 2];
#pragma unroll
    for (int n = 0; n < HIDD / 2; n++) acc2[n] = ov[OV_B2 + half * (HIDD / 2) + n];

    for (int m = 0; m < HIDD; m++) {
        float tm = ov[OV_B1 + m];
        const float4* w1r = (const float4*)&ov[OV_W1 + m * HD];
#pragma unroll
        for (int q = 0; q < HD / 4; q++) {
            float4 w = w1r[q];
            tm += hr[4 * q + 0] * w.x + hr[4 * q + 1] * w.y
                + hr[4 * q + 2] * w.z + hr[4 * q + 3] * w.w;
        }
        tm = 0.5f * tm * (1.0f + erff(tm * 0.70710678118654752f));
        const float4* w2r = (const float4*)&ov[OV_W2 + m * HIDD + half * (HIDD / 2)];
#pragma unroll
        for (int q = 0; q < HIDD / 8; q++) {
            float4 w = w2r[q];
            acc2[4 * q + 0] += tm * w.x; acc2[4 * q + 1] += tm * w.y;
            acc2[4 * q + 2] += tm * w.z; acc2[4 * q + 3] += tm * w.w;
        }
    }

    const int bS = tile * SPC + s;
    float4* op = (float4*)(out + ((size_t)bS * NBK + ib) * HIDD + half * (HIDD / 2));
#pragma unroll
    for (int q = 0; q < HIDD / 8; q++)
        op[q] = make_float4(acc2[4 * q], acc2[4 * q + 1],
                            acc2[4 * q + 2], acc2[4 * q + 3]);
}

extern "C" void kernel_launch(void* const* d_in, const int* in_sizes, int n_in,
                              void* d_out, int out_size)
{
    const float* x    = (const float*)d_in[0];
    const float* mask = (const float*)d_in[1];
    const float* Wih0 = (const float*)d_in[2];
    const float* Whh0 = (const float*)d_in[3];
    const float* bih0 = (const float*)d_in[4];
    const float* bhh0 = (const float*)d_in[5];
    const float* Wih1 = (const float*)d_in[6];
    const float* Whh1 = (const float*)d_in[7];
    const float* bih1 = (const float*)d_in[8];
    const float* bhh1 = (const float*)d_in[9];
    const float* W1   = (const float*)d_in[10];
    const float* b1   = (const float*)d_in[11];
    const float* W2   = (const float*)d_in[12];
    const float* b2   = (const float*)d_in[13];
    float* out = (float*)d_out;

    cudaFuncSetAttribute(lstm_wmma, cudaFuncAttributeMaxDynamicSharedMemorySize, SM_SZ);
    lstm_wmma<<<GRID, TPB, SM_SZ>>>(x, mask, Wih0, Whh0, bih0, bhh0,
                                    Wih1, Whh1, bih1, bhh1, W1, b1, W2, b2, out);
}

// round 16
// speedup vs baseline: 1.1842x; 1.1842x over previous
#include <cuda_runtime.h>
#include <cuda_bf16.h>
#include <mma.h>
#include <math.h>

using namespace nvcuda;

#define NBK  5
#define HD   32
#define DIN  4
#define TT   25
#define HIDD 64
#define TPB  256          // 8 warps; warp w owns gate cols [16w,16w+16) = j [4w,4w+4)
#define SPC  128
#define TILES 256
#define GRID (TILES*NBK)  // 1280

#define LDA 136           // A tiles col-major [k][sample], bf16
#define LDW 40            // W staging row-major [gate(4j+g)][k], bf16
#define LDX 24
#define LDD 132           // D f32 [sample][gate]

// ---- SMEM (bytes) ----
#define ATILE  8704       // one [32][136] bf16 tile
#define SM_A   0          // 8 tiles: A0H0,A0L0,A0H1,A0L1,A1H0,A1L0,A1H1,A1L1
#define SM_AX  69632      // [16][136] bf16 = 4352
#define SM_B0  73984      // bias0[128] f32 (row 4j+g)
#define SM_B1  74496
#define SM_D   75008      // 128x132 f32 = 67584; W staged here at start, MLP at end
#define SM_W0H 75008
#define SM_W0L 85248
#define SM_P1H 95488
#define SM_P1L 105728
#define SM_W1H 115968
#define SM_W1L 126208
#define SM_WX  136448     // [128][24] bf16 = 6144
#define SM_SZ  142592     // 1 CTA/SM

// MLP overlay (floats) into D region after recurrence
#define OVF   (SM_D/4)
#define OV_W1 (OVF+0)
#define OV_B1 (OVF+2048)
#define OV_W2 (OVF+2112)
#define OV_B2 (OVF+6208)

static __device__ __forceinline__ float tanhfast(float x) {
    float y; asm("tanh.approx.f32 %0, %1;" : "=f"(y) : "f"(x)); return y;
}
static __device__ __forceinline__ float sigf(float v) {
    return fmaf(0.5f, tanhfast(0.5f * v), 0.5f);
}

typedef wmma::fragment<wmma::matrix_a, 16, 16, 16, __nv_bfloat16, wmma::col_major> FragA;
typedef wmma::fragment<wmma::matrix_b, 16, 16, 16, __nv_bfloat16, wmma::col_major> FragB;
typedef wmma::fragment<wmma::accumulator, 16, 16, 16, float> FragC;

__global__ void __launch_bounds__(TPB, 1) lstm_wmma(
    const float* __restrict__ x,    const float* __restrict__ mask,
    const float* __restrict__ Wih0, const float* __restrict__ Whh0,
    const float* __restrict__ bih0, const float* __restrict__ bhh0,
    const float* __restrict__ Wih1, const float* __restrict__ Whh1,
    const float* __restrict__ bih1, const float* __restrict__ bhh1,
    const float* __restrict__ W1,   const float* __restrict__ b1,
    const float* __restrict__ W2,   const float* __restrict__ b2,
    float* __restrict__ out)
{
    extern __shared__ char sm[];
    const int tid  = threadIdx.x;
    const int wid  = tid >> 5;
    const int lane = tid & 31;
    const int ng   = wid * 16;                   // this warp's gate-column base
    const int ib   = 4 - (blockIdx.x >> 8);      // heavy blocks first
    const int tile = blockIdx.x & (TILES - 1);

    __nv_bfloat16* AX = (__nv_bfloat16*)(sm + SM_AX);
    __nv_bfloat16* WX = (__nv_bfloat16*)(sm + SM_WX);
    float* D   = (float*)(sm + SM_D);
    float* b0p = (float*)(sm + SM_B0);
    float* b1p = (float*)(sm + SM_B1);

    // ---- zero A tiles + AX ----
    for (int i = tid; i < (SM_AX + 4352) / 16; i += TPB)
        ((uint4*)sm)[i] = make_uint4(0, 0, 0, 0);
    for (int i = tid; i < 6144 / 16; i += TPB)
        ((uint4*)(sm + SM_WX))[i] = make_uint4(0, 0, 0, 0);

    // ---- stage weights (hi/lo bf16 split, gate rows r = 4j+g) into D overlay ----
    {
        const float* srcs[3] = { Whh0 + ib * 4096, Wih1 + ib * 4096, Whh1 + ib * 4096 };
        __nv_bfloat16* WH[3] = { (__nv_bfloat16*)(sm + SM_W0H),
                                 (__nv_bfloat16*)(sm + SM_P1H),
                                 (__nv_bfloat16*)(sm + SM_W1H) };
        __nv_bfloat16* WL[3] = { (__nv_bfloat16*)(sm + SM_W0L),
                                 (__nv_bfloat16*)(sm + SM_P1L),
                                 (__nv_bfloat16*)(sm + SM_W1L) };
        for (int idx = tid; idx < 3 * 128 * 32; idx += TPB) {
            int m = idx >> 12, t = idx & 4095, sr = t >> 5, k = t & 31;
            int r = 4 * (sr & 31) + (sr >> 5);
            float w = srcs[m][sr * 32 + k];
            __nv_bfloat16 hb = __float2bfloat16(w);
            WH[m][r * LDW + k] = hb;
            WL[m][r * LDW + k] = __float2bfloat16(w - __bfloat162float(hb));
        }
    }
    __syncthreads();   // WX zeros visible before scatter
    for (int idx = tid; idx < 128 * DIN; idx += TPB) {
        int sr = idx >> 2, k = idx & 3;
        int r = 4 * (sr & 31) + (sr >> 5);
        float w = Wih0[ib * 512 + sr * DIN + k];
        __nv_bfloat16 hb = __float2bfloat16(w);
        WX[r * LDX + k]     = hb;                                    // pairs xh
        WX[r * LDX + 4 + k] = __float2bfloat16(w - __bfloat162float(hb)); // pairs xh
        WX[r * LDX + 8 + k] = hb;                                    // pairs xl
    }
    if (tid < 128) {
        int r = 4 * (tid & 31) + (tid >> 5);
        b0p[r] = bih0[ib * 128 + tid] + bhh0[ib * 128 + tid];
        b1p[r] = bih1[ib * 128 + tid] + bhh1[ib * 128 + tid];
    }
    __syncthreads();

    // ---- hoist all 13 B (weight) fragments into registers ----
    FragB bh0[2], bl0[2], bp1h[2], bp1l[2], bw1h[2], bw1l[2], bx;
#pragma unroll
    for (int kt = 0; kt < 2; kt++) {
        wmma::load_matrix_sync(bh0[kt],  (__nv_bfloat16*)(sm + SM_W0H) + ng * LDW + kt * 16, LDW);
        wmma::load_matrix_sync(bl0[kt],  (__nv_bfloat16*)(sm + SM_W0L) + ng * LDW + kt * 16, LDW);
        wmma::load_matrix_sync(bp1h[kt], (__nv_bfloat16*)(sm + SM_P1H) + ng * LDW + kt * 16, LDW);
        wmma::load_matrix_sync(bp1l[kt], (__nv_bfloat16*)(sm + SM_P1L) + ng * LDW + kt * 16, LDW);
        wmma::load_matrix_sync(bw1h[kt], (__nv_bfloat16*)(sm + SM_W1H) + ng * LDW + kt * 16, LDW);
        wmma::load_matrix_sync(bw1l[kt], (__nv_bfloat16*)(sm + SM_W1L) + ng * LDW + kt * 16, LDW);
    }
    wmma::load_matrix_sync(bx, WX + ng * LDX, LDX);

    // ---- per-thread epilogue state: lane owns samples {32*s4+lane}, warp j {4w..} ----
    float c0r[16], c1r[16];
#pragma unroll
    for (int q = 0; q < 16; q++) { c0r[q] = 0.f; c1r[q] = 0.f; }

    const int Ti = 5 * (ib + 1);
    const float4* xb = (const float4*)x    + (size_t)(tile * SPC + (tid & 127)) * TT + (TT - Ti);
    const float4* mb = (const float4*)mask + (size_t)(tile * SPC + (tid & 127)) * TT + (TT - Ti);

    // stage AX(0)
    if (tid < 128) {
        float4 xv = __ldg(xb), mv = __ldg(mb);
        float xm[4] = { xv.x * mv.x, xv.y * mv.y, xv.z * mv.z, xv.w * mv.w };
#pragma unroll
        for (int k = 0; k < 4; k++) {
            __nv_bfloat16 hb = __float2bfloat16(xm[k]);
            AX[(k)     * LDA + tid] = hb;
            AX[(k + 4) * LDA + tid] = hb;
            AX[(k + 8) * LDA + tid] = __float2bfloat16(xm[k] - __bfloat162float(hb));
        }
    }

    for (int st = 0; st < Ti; st++) {
        __syncthreads();   // epi writes (A0,A1,AX) visible; W-frag reads done before D stores
        const int rb = st & 1, wb = 1 - rb;
        __nv_bfloat16* A0Hr = (__nv_bfloat16*)(sm + SM_A + (2 * rb) * ATILE);
        __nv_bfloat16* A0Lr = A0Hr + ATILE / 2;
        __nv_bfloat16* A0Hw = (__nv_bfloat16*)(sm + SM_A + (2 * wb) * ATILE);
        __nv_bfloat16* A0Lw = A0Hw + ATILE / 2;
        __nv_bfloat16* A1Hr = (__nv_bfloat16*)(sm + SM_A + (4 + 2 * rb) * ATILE);
        __nv_bfloat16* A1Lr = A1Hr + ATILE / 2;
        __nv_bfloat16* A1Hw = (__nv_bfloat16*)(sm + SM_A + (4 + 2 * wb) * ATILE);
        __nv_bfloat16* A1Lw = A1Hw + ATILE / 2;

        // ================= L0 MMA: warp covers all 8 m-tiles for its 16 cols ====
        for (int m = 0; m < 8; m++) {
            FragC c;
            wmma::fill_fragment(c, 0.0f);
#pragma unroll
            for (int kt = 0; kt < 2; kt++) {
                FragA ahh, ahl;
                wmma::load_matrix_sync(ahh, A0Hr + kt * 16 * LDA + m * 16, LDA);
                wmma::load_matrix_sync(ahl, A0Lr + kt * 16 * LDA + m * 16, LDA);
                wmma::mma_sync(c, ahh, bh0[kt], c);
                wmma::mma_sync(c, ahh, bl0[kt], c);
                wmma::mma_sync(c, ahl, bh0[kt], c);
            }
            FragA ax;
            wmma::load_matrix_sync(ax, AX + m * 16, LDA);
            wmma::mma_sync(c, ax, bx, c);
            wmma::store_matrix_sync(D + m * 16 * LDD + ng, c, LDD, wmma::mem_row_major);
        }
        __syncwarp();      // own D cols visible to own lanes

        // ---- epi0 (warp-local: 128 samples x 4 j) ----
#pragma unroll
        for (int s4 = 0; s4 < 4; s4++) {
            const int s = 32 * s4 + lane;
#pragma unroll
            for (int jq = 0; jq < 4; jq++) {
                const int ci = 4 * s4 + jq;
                float4 gg = *(const float4*)(D + s * LDD + ng + 4 * jq);
                float4 bb = *(const float4*)(b0p + ng + 4 * jq);
                float ai = gg.x + bb.x, af = gg.y + bb.y;
                float ag = gg.z + bb.z, ao = gg.w + bb.w;
                float cc = sigf(af) * c0r[ci] + sigf(ai) * tanhfast(ag);
                c0r[ci] = cc;
                float h = sigf(ao) * tanhfast(cc);
                const int j = 4 * wid + jq;
                __nv_bfloat16 hb = __float2bfloat16(h);
                A0Hw[j * LDA + s] = hb;
                A0Lw[j * LDA + s] = __float2bfloat16(h - __bfloat162float(hb));
            }
        }
        __syncthreads();   // A0[wb] (all warps) visible

        // ================= L1 MMA =================
        for (int m = 0; m < 8; m++) {
            FragC c;
            wmma::fill_fragment(c, 0.0f);
#pragma unroll
            for (int kt = 0; kt < 2; kt++) {
                FragA ahh, ahl;
                wmma::load_matrix_sync(ahh, A0Hw + kt * 16 * LDA + m * 16, LDA);
                wmma::load_matrix_sync(ahl, A0Lw + kt * 16 * LDA + m * 16, LDA);
                wmma::mma_sync(c, ahh, bp1h[kt], c);
                wmma::mma_sync(c, ahh, bp1l[kt], c);
                wmma::mma_sync(c, ahl, bp1h[kt], c);
            }
#pragma unroll
            for (int kt = 0; kt < 2; kt++) {
                FragA ahh, ahl;
                wmma::load_matrix_sync(ahh, A1Hr + kt * 16 * LDA + m * 16, LDA);
                wmma::load_matrix_sync(ahl, A1Lr + kt * 16 * LDA + m * 16, LDA);
                wmma::mma_sync(c, ahh, bw1h[kt], c);
                wmma::mma_sync(c, ahh, bw1l[kt], c);
                wmma::mma_sync(c, ahl, bw1h[kt], c);
            }
            wmma::store_matrix_sync(D + m * 16 * LDD + ng, c, LDD, wmma::mem_row_major);
        }
        __syncwarp();

        // ---- epi1 (warp-local) + stage AX(st+1) ----
#pragma unroll
        for (int s4 = 0; s4 < 4; s4++) {
            const int s = 32 * s4 + lane;
#pragma unroll
            for (int jq = 0; jq < 4; jq++) {
                const int ci = 4 * s4 + jq;
                float4 gg = *(const float4*)(D + s * LDD + ng + 4 * jq);
                float4 bb = *(const float4*)(b1p + ng + 4 * jq);
                float ai = gg.x + bb.x, af = gg.y + bb.y;
                float ag = gg.z + bb.z, ao = gg.w + bb.w;
                float cc = sigf(af) * c1r[ci] + sigf(ai) * tanhfast(ag);
                c1r[ci] = cc;
                float h = sigf(ao) * tanhfast(cc);
                const int j = 4 * wid + jq;
                __nv_bfloat16 hb = __float2bfloat16(h);
                A1Hw[j * LDA + s] = hb;
                A1Lw[j * LDA + s] = __float2bfloat16(h - __bfloat162float(hb));
            }
        }
        if (st + 1 < Ti && tid < 128) {
            float4 xv = __ldg(xb + st + 1), mv = __ldg(mb + st + 1);
            float xm[4] = { xv.x * mv.x, xv.y * mv.y, xv.z * mv.z, xv.w * mv.w };
#pragma unroll
            for (int k = 0; k < 4; k++) {
                __nv_bfloat16 hb = __float2bfloat16(xm[k]);
                AX[(k)     * LDA + tid] = hb;
                AX[(k + 4) * LDA + tid] = hb;
                AX[(k + 8) * LDA + tid] = __float2bfloat16(xm[k] - __bfloat162float(hb));
            }
        }
        // next top-of-loop __syncthreads publishes A1[wb] + AX
    }
    __syncthreads();

    // ---- final h1 (hi+lo) ----
    const int fb = 1 - ((Ti - 1) & 1);
    const int s  = tid & 127;
    const int jh = tid >> 7;
    __nv_bfloat16* A1Hf = (__nv_bfloat16*)(sm + SM_A + (4 + 2 * fb) * ATILE);
    __nv_bfloat16* A1Lf = A1Hf + ATILE / 2;
    float hr[HD];
#pragma unroll
    for (int k = 0; k < HD; k++)
        hr[k] = __bfloat162float(A1Hf[k * LDA + s]) + __bfloat162float(A1Lf[k * LDA + s]);
    __syncthreads();

    // ---- MLP head (overlay into D region) ----
    float* ov = (float*)sm;
    for (int idx = tid; idx < HIDD * HD; idx += TPB)   ov[OV_W1 + idx] = W1[idx];
    for (int idx = tid; idx < HIDD * HIDD; idx += TPB) {
        int n = idx / HIDD, m = idx % HIDD;
        ov[OV_W2 + m * HIDD + n] = W2[idx];
    }
    if (tid < HIDD) { ov[OV_B1 + tid] = b1[tid]; ov[OV_B2 + tid] = b2[tid]; }
    __syncthreads();

    float acc2[HIDD / 2];
#pragma unroll
    for (int n = 0; n < HIDD / 2; n++) acc2[n] = ov[OV_B2 + jh * (HIDD / 2) + n];

    for (int m = 0; m < HIDD; m++) {
        float tm = ov[OV_B1 + m];
        const float4* w1r = (const float4*)&ov[OV_W1 + m * HD];
#pragma unroll
        for (int q = 0; q < HD / 4; q++) {
            float4 w = w1r[q];
            tm += hr[4 * q + 0] * w.x + hr[4 * q + 1] * w.y
                + hr[4 * q + 2] * w.z + hr[4 * q + 3] * w.w;
        }
        tm = 0.5f * tm * (1.0f + erff(tm * 0.70710678118654752f));
        const float4* w2r = (const float4*)&ov[OV_W2 + m * HIDD + jh * (HIDD / 2)];
#pragma unroll
        for (int q = 0; q < HIDD / 8; q++) {
            float4 w = w2r[q];
            acc2[4 * q + 0] += tm * w.x; acc2[4 * q + 1] += tm * w.y;
            acc2[4 * q + 2] += tm * w.z; acc2[4 * q + 3] += tm * w.w;
        }
    }

    const int bS = tile * SPC + s;
    float4* op = (float4*)(out + ((size_t)bS * NBK + ib) * HIDD + jh * (HIDD / 2));
#pragma unroll
    for (int q = 0; q < HIDD / 8; q++)
        op[q] = make_float4(acc2[4 * q], acc2[4 * q + 1],
                            acc2[4 * q + 2], acc2[4 * q + 3]);
}

extern "C" void kernel_launch(void* const* d_in, const int* in_sizes, int n_in,
                              void* d_out, int out_size)
{
    const float* x    = (const float*)d_in[0];
    const float* mask = (const float*)d_in[1];
    const float* Wih0 = (const float*)d_in[2];
    const float* Whh0 = (const float*)d_in[3];
    const float* bih0 = (const float*)d_in[4];
    const float* bhh0 = (const float*)d_in[5];
    const float* Wih1 = (const float*)d_in[6];
    const float* Whh1 = (const float*)d_in[7];
    const float* bih1 = (const float*)d_in[8];
    const float* bhh1 = (const float*)d_in[9];
    const float* W1   = (const float*)d_in[10];
    const float* b1   = (const float*)d_in[11];
    const float* W2   = (const float*)d_in[12];
    const float* b2   = (const float*)d_in[13];
    float* out = (float*)d_out;

    cudaFuncSetAttribute(lstm_wmma, cudaFuncAttributeMaxDynamicSharedMemorySize, SM_SZ);
    lstm_wmma<<<GRID, TPB, SM_SZ>>>(x, mask, Wih0, Whh0, bih0, bhh0,
                                    Wih1, Whh1, bih1, bhh1, W1, b1, W2, b2, out);
}

// round 17
// speedup vs baseline: 1.5146x; 1.2791x over previous
#include <cuda_runtime.h>
#include <cuda_bf16.h>
#include <mma.h>
#include <math.h>

using namespace nvcuda;

#define NBK  5
#define HD   32
#define DIN  4
#define TT   25
#define HIDD 64
#define TPB  256          // 8 warps; warp w owns gate cols [16w,16w+16) = j [4w,4w+4)
#define SPC  128
#define TILES 256
#define GRID (TILES*NBK)  // 1280

#define LDA 136           // A tiles col-major [k][sample], bf16
#define LDW 40            // W staging row-major [gate(4j+g)][k], bf16
#define LDX 24
#define LDD 132           // D f32 [sample][gate]

// ---- SMEM (bytes) ----
#define ATILE  8704       // one [32][136] bf16 tile
#define SM_A   0          // 4 tiles: A0H, A0L, A1H, A1L (single-buffered)
#define SM_AX  34816      // [16][136] bf16 = 4352
#define SM_B0  39168      // bias0[128] f32 (row 4j+g)
#define SM_B1  39680
#define SM_D   40192      // 128x132 f32 = 67584; W staged inside, MLP overlay at end
#define SM_W0H (SM_D+0)
#define SM_W0L (SM_D+10240)
#define SM_P1H (SM_D+20480)
#define SM_P1L (SM_D+30720)
#define SM_W1H (SM_D+40960)
#define SM_W1L (SM_D+51200)
#define SM_WX  (SM_D+61440)   // [128][24] bf16 = 6144; ends exactly at D end
#define SM_SZ  107776     // -> 2 CTAs/SM (16 warps)

// MLP overlay (floats) into D region after recurrence
#define OVF   (SM_D/4)
#define OV_W1 (OVF+0)
#define OV_B1 (OVF+2048)
#define OV_W2 (OVF+2112)
#define OV_B2 (OVF+6208)

static __device__ __forceinline__ float tanhfast(float x) {
    float y; asm("tanh.approx.f32 %0, %1;" : "=f"(y) : "f"(x)); return y;
}
static __device__ __forceinline__ float sigf(float v) {
    return fmaf(0.5f, tanhfast(0.5f * v), 0.5f);
}

typedef wmma::fragment<wmma::matrix_a, 16, 16, 16, __nv_bfloat16, wmma::col_major> FragA;
typedef wmma::fragment<wmma::matrix_b, 16, 16, 16, __nv_bfloat16, wmma::col_major> FragB;
typedef wmma::fragment<wmma::accumulator, 16, 16, 16, float> FragC;

__global__ void __launch_bounds__(TPB, 2) lstm_wmma(
    const float* __restrict__ x,    const float* __restrict__ mask,
    const float* __restrict__ Wih0, const float* __restrict__ Whh0,
    const float* __restrict__ bih0, const float* __restrict__ bhh0,
    const float* __restrict__ Wih1, const float* __restrict__ Whh1,
    const float* __restrict__ bih1, const float* __restrict__ bhh1,
    const float* __restrict__ W1,   const float* __restrict__ b1,
    const float* __restrict__ W2,   const float* __restrict__ b2,
    float* __restrict__ out)
{
    extern __shared__ char sm[];
    const int tid  = threadIdx.x;
    const int wid  = tid >> 5;
    const int lane = tid & 31;
    const int ng   = wid * 16;                   // this warp's gate-column base
    const int ib   = 4 - (blockIdx.x >> 8);      // heavy blocks first
    const int tile = blockIdx.x & (TILES - 1);

    __nv_bfloat16* A0H = (__nv_bfloat16*)(sm + SM_A);
    __nv_bfloat16* A0L = (__nv_bfloat16*)(sm + SM_A + ATILE);
    __nv_bfloat16* A1H = (__nv_bfloat16*)(sm + SM_A + 2 * ATILE);
    __nv_bfloat16* A1L = (__nv_bfloat16*)(sm + SM_A + 3 * ATILE);
    __nv_bfloat16* AX  = (__nv_bfloat16*)(sm + SM_AX);
    __nv_bfloat16* WX  = (__nv_bfloat16*)(sm + SM_WX);
    float* D   = (float*)(sm + SM_D);
    float* b0p = (float*)(sm + SM_B0);
    float* b1p = (float*)(sm + SM_B1);

    // ---- zero A tiles + AX (h init = 0; pads stay 0) and WX pads ----
    for (int i = tid; i < (SM_AX + 4352) / 16; i += TPB)
        ((uint4*)sm)[i] = make_uint4(0, 0, 0, 0);
    for (int i = tid; i < 6144 / 16; i += TPB)
        ((uint4*)(sm + SM_WX))[i] = make_uint4(0, 0, 0, 0);

    // ---- stage weights (hi/lo bf16 split, gate rows r = 4j+g) into D overlay ----
    {
        const float* srcs[3] = { Whh0 + ib * 4096, Wih1 + ib * 4096, Whh1 + ib * 4096 };
        __nv_bfloat16* WH[3] = { (__nv_bfloat16*)(sm + SM_W0H),
                                 (__nv_bfloat16*)(sm + SM_P1H),
                                 (__nv_bfloat16*)(sm + SM_W1H) };
        __nv_bfloat16* WL[3] = { (__nv_bfloat16*)(sm + SM_W0L),
                                 (__nv_bfloat16*)(sm + SM_P1L),
                                 (__nv_bfloat16*)(sm + SM_W1L) };
        for (int idx = tid; idx < 3 * 128 * 32; idx += TPB) {
            int m = idx >> 12, t = idx & 4095, sr = t >> 5, k = t & 31;
            int r = 4 * (sr & 31) + (sr >> 5);
            float w = srcs[m][sr * 32 + k];
            __nv_bfloat16 hb = __float2bfloat16(w);
            WH[m][r * LDW + k] = hb;
            WL[m][r * LDW + k] = __float2bfloat16(w - __bfloat162float(hb));
        }
    }
    __syncthreads();   // WX zeros visible before scatter
    for (int idx = tid; idx < 128 * DIN; idx += TPB) {
        int sr = idx >> 2, k = idx & 3;
        int r = 4 * (sr & 31) + (sr >> 5);
        float w = Wih0[ib * 512 + sr * DIN + k];
        __nv_bfloat16 hb = __float2bfloat16(w);
        WX[r * LDX + k]     = hb;                                         // pairs xh
        WX[r * LDX + 4 + k] = __float2bfloat16(w - __bfloat162float(hb)); // pairs xh
        WX[r * LDX + 8 + k] = hb;                                         // pairs xl
    }
    if (tid < 128) {
        int r = 4 * (tid & 31) + (tid >> 5);
        b0p[r] = bih0[ib * 128 + tid] + bhh0[ib * 128 + tid];
        b1p[r] = bih1[ib * 128 + tid] + bhh1[ib * 128 + tid];
    }
    __syncthreads();

    // ---- hoist all 13 B (weight) fragments into registers ----
    FragB bh0[2], bl0[2], bp1h[2], bp1l[2], bw1h[2], bw1l[2], bx;
#pragma unroll
    for (int kt = 0; kt < 2; kt++) {
        wmma::load_matrix_sync(bh0[kt],  (__nv_bfloat16*)(sm + SM_W0H) + ng * LDW + kt * 16, LDW);
        wmma::load_matrix_sync(bl0[kt],  (__nv_bfloat16*)(sm + SM_W0L) + ng * LDW + kt * 16, LDW);
        wmma::load_matrix_sync(bp1h[kt], (__nv_bfloat16*)(sm + SM_P1H) + ng * LDW + kt * 16, LDW);
        wmma::load_matrix_sync(bp1l[kt], (__nv_bfloat16*)(sm + SM_P1L) + ng * LDW + kt * 16, LDW);
        wmma::load_matrix_sync(bw1h[kt], (__nv_bfloat16*)(sm + SM_W1H) + ng * LDW + kt * 16, LDW);
        wmma::load_matrix_sync(bw1l[kt], (__nv_bfloat16*)(sm + SM_W1L) + ng * LDW + kt * 16, LDW);
    }
    wmma::load_matrix_sync(bx, WX + ng * LDX, LDX);

    // ---- per-thread epilogue state ----
    float c0r[16], c1r[16];
#pragma unroll
    for (int q = 0; q < 16; q++) { c0r[q] = 0.f; c1r[q] = 0.f; }

    const int Ti = 5 * (ib + 1);
    const float4* xb = (const float4*)x    + (size_t)(tile * SPC + (tid & 127)) * TT + (TT - Ti);
    const float4* mb = (const float4*)mask + (size_t)(tile * SPC + (tid & 127)) * TT + (TT - Ti);

    // stage AX(0)
    if (tid < 128) {
        float4 xv = __ldg(xb), mv = __ldg(mb);
        float xm[4] = { xv.x * mv.x, xv.y * mv.y, xv.z * mv.z, xv.w * mv.w };
#pragma unroll
        for (int k = 0; k < 4; k++) {
            __nv_bfloat16 hb = __float2bfloat16(xm[k]);
            AX[(k)     * LDA + tid] = hb;
            AX[(k + 4) * LDA + tid] = hb;
            AX[(k + 8) * LDA + tid] = __float2bfloat16(xm[k] - __bfloat162float(hb));
        }
    }

    for (int st = 0; st < Ti; st++) {
        __syncthreads();   // epi1 writes (A1, AX) of prev step visible; frag/W reads done

        // ================= L0 MMA: D = h0*Wh0(split) + x*Wx =================
        for (int m = 0; m < 8; m++) {
            FragC c;
            wmma::fill_fragment(c, 0.0f);
#pragma unroll
            for (int kt = 0; kt < 2; kt++) {
                FragA ahh, ahl;
                wmma::load_matrix_sync(ahh, A0H + kt * 16 * LDA + m * 16, LDA);
                wmma::load_matrix_sync(ahl, A0L + kt * 16 * LDA + m * 16, LDA);
                wmma::mma_sync(c, ahh, bh0[kt], c);
                wmma::mma_sync(c, ahh, bl0[kt], c);
                wmma::mma_sync(c, ahl, bh0[kt], c);
            }
            FragA ax;
            wmma::load_matrix_sync(ax, AX + m * 16, LDA);
            wmma::mma_sync(c, ax, bx, c);
            wmma::store_matrix_sync(D + m * 16 * LDD + ng, c, LDD, wmma::mem_row_major);
        }
        __syncthreads();   // all L0 reads of A0 complete; D visible

        // ---- epi0 (warp-local cols): read D, write A0 (single buffer) ----
#pragma unroll
        for (int s4 = 0; s4 < 4; s4++) {
            const int s = 32 * s4 + lane;
#pragma unroll
            for (int jq = 0; jq < 4; jq++) {
                const int ci = 4 * s4 + jq;
                float4 gg = *(const float4*)(D + s * LDD + ng + 4 * jq);
                float4 bb = *(const float4*)(b0p + ng + 4 * jq);
                float ai = gg.x + bb.x, af = gg.y + bb.y;
                float ag = gg.z + bb.z, ao = gg.w + bb.w;
                float cc = sigf(af) * c0r[ci] + sigf(ai) * tanhfast(ag);
                c0r[ci] = cc;
                float h = sigf(ao) * tanhfast(cc);
                const int j = 4 * wid + jq;
                __nv_bfloat16 hb = __float2bfloat16(h);
                A0H[j * LDA + s] = hb;
                A0L[j * LDA + s] = __float2bfloat16(h - __bfloat162float(hb));
            }
        }
        __syncthreads();   // new A0 visible

        // ================= L1 MMA: D = h0new*Wp1 + h1*Wh1 =================
        for (int m = 0; m < 8; m++) {
            FragC c;
            wmma::fill_fragment(c, 0.0f);
#pragma unroll
            for (int kt = 0; kt < 2; kt++) {
                FragA ahh, ahl;
                wmma::load_matrix_sync(ahh, A0H + kt * 16 * LDA + m * 16, LDA);
                wmma::load_matrix_sync(ahl, A0L + kt * 16 * LDA + m * 16, LDA);
                wmma::mma_sync(c, ahh, bp1h[kt], c);
                wmma::mma_sync(c, ahh, bp1l[kt], c);
                wmma::mma_sync(c, ahl, bp1h[kt], c);
            }
#pragma unroll
            for (int kt = 0; kt < 2; kt++) {
                FragA ahh, ahl;
                wmma::load_matrix_sync(ahh, A1H + kt * 16 * LDA + m * 16, LDA);
                wmma::load_matrix_sync(ahl, A1L + kt * 16 * LDA + m * 16, LDA);
                wmma::mma_sync(c, ahh, bw1h[kt], c);
                wmma::mma_sync(c, ahh, bw1l[kt], c);
                wmma::mma_sync(c, ahl, bw1h[kt], c);
            }
            wmma::store_matrix_sync(D + m * 16 * LDD + ng, c, LDD, wmma::mem_row_major);
        }
        __syncthreads();   // all L1 reads of A1 complete; D visible

        // ---- epi1: read D, write A1; stage AX(st+1) ----
#pragma unroll
        for (int s4 = 0; s4 < 4; s4++) {
            const int s = 32 * s4 + lane;
#pragma unroll
            for (int jq = 0; jq < 4; jq++) {
                const int ci = 4 * s4 + jq;
                float4 gg = *(const float4*)(D + s * LDD + ng + 4 * jq);
                float4 bb = *(const float4*)(b1p + ng + 4 * jq);
                float ai = gg.x + bb.x, af = gg.y + bb.y;
                float ag = gg.z + bb.z, ao = gg.w + bb.w;
                float cc = sigf(af) * c1r[ci] + sigf(ai) * tanhfast(ag);
                c1r[ci] = cc;
                float h = sigf(ao) * tanhfast(cc);
                const int j = 4 * wid + jq;
                __nv_bfloat16 hb = __float2bfloat16(h);
                A1H[j * LDA + s] = hb;
                A1L[j * LDA + s] = __float2bfloat16(h - __bfloat162float(hb));
            }
        }
        if (st + 1 < Ti && tid < 128) {
            float4 xv = __ldg(xb + st + 1), mv = __ldg(mb + st + 1);
            float xm[4] = { xv.x * mv.x, xv.y * mv.y, xv.z * mv.z, xv.w * mv.w };
#pragma unroll
            for (int k = 0; k < 4; k++) {
                __nv_bfloat16 hb = __float2bfloat16(xm[k]);
                AX[(k)     * LDA + tid] = hb;
                AX[(k + 4) * LDA + tid] = hb;
                AX[(k + 8) * LDA + tid] = __float2bfloat16(xm[k] - __bfloat162float(hb));
            }
        }
        // next top-of-loop __syncthreads publishes A1 + AX
    }
    __syncthreads();

    // ---- final h1 (hi+lo) ----
    const int s  = tid & 127;
    const int jh = tid >> 7;
    float hr[HD];
#pragma unroll
    for (int k = 0; k < HD; k++)
        hr[k] = __bfloat162float(A1H[k * LDA + s]) + __bfloat162float(A1L[k * LDA + s]);
    __syncthreads();

    // ---- MLP head (overlay into D region) ----
    float* ov = (float*)sm;
    for (int idx = tid; idx < HIDD * HD; idx += TPB)   ov[OV_W1 + idx] = W1[idx];
    for (int idx = tid; idx < HIDD * HIDD; idx += TPB) {
        int n = idx / HIDD, m = idx % HIDD;
        ov[OV_W2 + m * HIDD + n] = W2[idx];
    }
    if (tid < HIDD) { ov[OV_B1 + tid] = b1[tid]; ov[OV_B2 + tid] = b2[tid]; }
    __syncthreads();

    float acc2[HIDD / 2];
#pragma unroll
    for (int n = 0; n < HIDD / 2; n++) acc2[n] = ov[OV_B2 + jh * (HIDD / 2) + n];

    for (int m = 0; m < HIDD; m++) {
        float tm = ov[OV_B1 + m];
        const float4* w1r = (const float4*)&ov[OV_W1 + m * HD];
#pragma unroll
        for (int q = 0; q < HD / 4; q++) {
            float4 w = w1r[q];
            tm += hr[4 * q + 0] * w.x + hr[4 * q + 1] * w.y
                + hr[4 * q + 2] * w.z + hr[4 * q + 3] * w.w;
        }
        tm = 0.5f * tm * (1.0f + erff(tm * 0.70710678118654752f));
        const float4* w2r = (const float4*)&ov[OV_W2 + m * HIDD + jh * (HIDD / 2)];
#pragma unroll
        for (int q = 0; q < HIDD / 8; q++) {
            float4 w = w2r[q];
            acc2[4 * q + 0] += tm * w.x; acc2[4 * q + 1] += tm * w.y;
            acc2[4 * q + 2] += tm * w.z; acc2[4 * q + 3] += tm * w.w;
        }
    }

    const int bS = tile * SPC + s;
    float4* op = (float4*)(out + ((size_t)bS * NBK + ib) * HIDD + jh * (HIDD / 2));
#pragma unroll
    for (int q = 0; q < HIDD / 8; q++)
        op[q] = make_float4(acc2[4 * q], acc2[4 * q + 1],
                            acc2[4 * q + 2], acc2[4 * q + 3]);
}

extern "C" void kernel_launch(void* const* d_in, const int* in_sizes, int n_in,
                              void* d_out, int out_size)
{
    const float* x    = (const float*)d_in[0];
    const float* mask = (const float*)d_in[1];
    const float* Wih0 = (const float*)d_in[2];
    const float* Whh0 = (const float*)d_in[3];
    const float* bih0 = (const float*)d_in[4];
    const float* bhh0 = (const float*)d_in[5];
    const float* Wih1 = (const float*)d_in[6];
    const float* Whh1 = (const float*)d_in[7];
    const float* bih1 = (const float*)d_in[8];
    const float* bhh1 = (const float*)d_in[9];
    const float* W1   = (const float*)d_in[10];
    const float* b1   = (const float*)d_in[11];
    const float* W2   = (const float*)d_in[12];
    const float* b2   = (const float*)d_in[13];
    float* out = (float*)d_out;

    cudaFuncSetAttribute(lstm_wmma, cudaFuncAttributeMaxDynamicSharedMemorySize, SM_SZ);
    lstm_wmma<<<GRID, TPB, SM_SZ>>>(x, mask, Wih0, Whh0, bih0, bhh0,
                                    Wih1, Whh1, bih1, bhh1, W1, b1, W2, b2, out);
}